// round 4
// baseline (speedup 1.0000x reference)
#include <cuda_runtime.h>
#include <cstdint>

// Problem constants
#define BB   4
#define SS   1024
#define DIN  768
#define HH   12
#define DH   64

// Scratch (device globals: no allocs allowed). All attn inputs pre-converted
// to tf32 bit patterns by the projection kernel.
__device__ uint32_t g_Qb[BB*HH*SS*DH];   // [b,h,s,e] tf32(big)
__device__ uint32_t g_Qs[BB*HH*SS*DH];   // [b,h,s,e] tf32(residual)
__device__ uint32_t g_Kb[BB*HH*SS*DH];   // [b,h,s,e] tf32(big)
__device__ uint32_t g_Ks[BB*HH*SS*DH];   // [b,h,s,e] tf32(residual)
__device__ uint32_t g_Vt[BB*HH*DH*SS];   // [b,h,e,s] tf32

// ---------------------------------------------------------------------------
// helpers
// ---------------------------------------------------------------------------
__device__ __forceinline__ uint32_t f2tf32(float f) {
    uint32_t r;
    asm("cvt.rna.tf32.f32 %0, %1;" : "=r"(r) : "f"(f));
    return r;
}

__device__ __forceinline__ void mma_tf32(float c[4],
                                         uint32_t a0, uint32_t a1, uint32_t a2, uint32_t a3,
                                         uint32_t b0, uint32_t b1) {
    asm volatile(
        "mma.sync.aligned.m16n8k8.row.col.f32.tf32.tf32.f32 "
        "{%0,%1,%2,%3}, {%4,%5,%6,%7}, {%8,%9}, {%0,%1,%2,%3};"
        : "+f"(c[0]), "+f"(c[1]), "+f"(c[2]), "+f"(c[3])
        : "r"(a0), "r"(a1), "r"(a2), "r"(a3), "r"(b0), "r"(b1));
}

__device__ __forceinline__ void cpa16(uint32_t smem_addr, const void* gptr) {
    asm volatile("cp.async.cg.shared.global [%0], [%1], 16;"
                 :: "r"(smem_addr), "l"(gptr));
}
__device__ __forceinline__ void cpa_commit() {
    asm volatile("cp.async.commit_group;");
}
template <int N>
__device__ __forceinline__ void cpa_wait() {
    asm volatile("cp.async.wait_group %0;" :: "n"(N));
}

// ---------------------------------------------------------------------------
// Kernel 1: fused QKV projection via tf32 mma, double-buffered smem.
// grid (4096/128, 12); 512 threads (16 warps: 4 in M x 4 in N).
// Epilogue writes tf32 bit patterns (Q,K split big/small; V transposed).
// ---------------------------------------------------------------------------
#define XSTR 36
#define WSTR 72
#define XW   (128*XSTR)      // 4608 words per X stage
#define WW   (3*32*WSTR)     // 6912 words per W stage

__global__ __launch_bounds__(512, 1)
void qkv_proj_kernel(const float* __restrict__ x,
                     const float* __restrict__ Wq,
                     const float* __restrict__ Wk,
                     const float* __restrict__ Wv) {
    extern __shared__ uint32_t psm[];
    // layout: Xs[2] then Ws[2]
    uint32_t* Xs[2] = { psm, psm + XW };
    uint32_t* Ws[2] = { psm + 2*XW, psm + 2*XW + WW };

    const int tid = threadIdx.x;
    const int wid = tid >> 5, lane = tid & 31;
    const int tg = lane >> 2, tig = lane & 3;
    const int wm = wid >> 2, wn = wid & 3;
    const int h = blockIdx.y;
    const int rowblk = blockIdx.x * 128;

    const float* xb = x + (size_t)rowblk * DIN;
    const float* wp[3] = { Wq + (size_t)h * DIN * DH,
                           Wk + (size_t)h * DIN * DH,
                           Wv + (size_t)h * DIN * DH };

    float acc[3][2][2][4];
    #pragma unroll
    for (int m = 0; m < 3; m++)
        #pragma unroll
        for (int i = 0; i < 2; i++)
            #pragma unroll
            for (int j = 0; j < 2; j++)
                #pragma unroll
                for (int r = 0; r < 4; r++) acc[m][i][j][r] = 0.f;

    const int wk_ = tid >> 4, wn4 = (tid & 15) * 4;

    float4 xv[2], wv[3];
    // preload chunk 0
    #pragma unroll
    for (int it = 0; it < 2; it++) {
        int idx = tid + it*512, row = idx >> 3, c4 = (idx & 7) * 4;
        xv[it] = *(const float4*)&xb[(size_t)row*DIN + c4];
    }
    #pragma unroll
    for (int m = 0; m < 3; m++)
        wv[m] = *(const float4*)&wp[m][(size_t)wk_*DH + wn4];

    for (int kc = 0; kc < DIN/32; kc++) {
        const int buf = kc & 1;
        // store staged chunk (uint4 STS)
        #pragma unroll
        for (int it = 0; it < 2; it++) {
            int idx = tid + it*512, row = idx >> 3, c4 = (idx & 7) * 4;
            *(uint4*)&Xs[buf][row*XSTR + c4] =
                make_uint4(f2tf32(xv[it].x), f2tf32(xv[it].y),
                           f2tf32(xv[it].z), f2tf32(xv[it].w));
        }
        #pragma unroll
        for (int m = 0; m < 3; m++) {
            *(uint4*)&Ws[buf][m*32*WSTR + wk_*WSTR + wn4] =
                make_uint4(f2tf32(wv[m].x), f2tf32(wv[m].y),
                           f2tf32(wv[m].z), f2tf32(wv[m].w));
        }
        __syncthreads();

        // prefetch next chunk (overlaps mma)
        if (kc + 1 < DIN/32) {
            int k0n = (kc + 1) * 32;
            #pragma unroll
            for (int it = 0; it < 2; it++) {
                int idx = tid + it*512, row = idx >> 3, c4 = (idx & 7) * 4;
                xv[it] = *(const float4*)&xb[(size_t)row*DIN + k0n + c4];
            }
            #pragma unroll
            for (int m = 0; m < 3; m++)
                wv[m] = *(const float4*)&wp[m][(size_t)(k0n + wk_)*DH + wn4];
        }

        #pragma unroll
        for (int kk = 0; kk < 4; kk++) {
            const int k0 = kk * 8;
            uint32_t a[2][4];
            #pragma unroll
            for (int ms = 0; ms < 2; ms++) {
                int r0 = wm*32 + ms*16 + tg;
                a[ms][0] = Xs[buf][(r0    )*XSTR + k0 + tig    ];
                a[ms][1] = Xs[buf][(r0 + 8)*XSTR + k0 + tig    ];
                a[ms][2] = Xs[buf][(r0    )*XSTR + k0 + tig + 4];
                a[ms][3] = Xs[buf][(r0 + 8)*XSTR + k0 + tig + 4];
            }
            #pragma unroll
            for (int m = 0; m < 3; m++) {
                #pragma unroll
                for (int j = 0; j < 2; j++) {
                    int n0 = wn*16 + j*8 + tg;
                    uint32_t b0 = Ws[buf][m*32*WSTR + (k0 + tig    )*WSTR + n0];
                    uint32_t b1 = Ws[buf][m*32*WSTR + (k0 + tig + 4)*WSTR + n0];
                    #pragma unroll
                    for (int ms = 0; ms < 2; ms++)
                        mma_tf32(acc[m][ms][j], a[ms][0], a[ms][1], a[ms][2], a[ms][3], b0, b1);
                }
            }
        }
    }

    // Epilogue: tf32 bit patterns.
    const int b = rowblk >> 10;
    const int s0 = rowblk & 1023;
    const size_t base = (((size_t)b*HH + h)*SS);
    #pragma unroll
    for (int ms = 0; ms < 2; ms++) {
        int r0 = s0 + wm*32 + ms*16 + tg;
        #pragma unroll
        for (int j = 0; j < 2; j++) {
            int c0 = wn*16 + j*8 + tig*2;
            // Q big/small
            #pragma unroll
            for (int half = 0; half < 2; half++) {
                size_t off = (base + r0 + half*8)*DH + c0;
                float v0 = acc[0][ms][j][half*2], v1 = acc[0][ms][j][half*2+1];
                uint32_t b0 = f2tf32(v0), b1 = f2tf32(v1);
                *(uint2*)&g_Qb[off] = make_uint2(b0, b1);
                *(uint2*)&g_Qs[off] = make_uint2(f2tf32(v0 - __uint_as_float(b0)),
                                                 f2tf32(v1 - __uint_as_float(b1)));
                // K big/small
                float k0v = acc[1][ms][j][half*2], k1v = acc[1][ms][j][half*2+1];
                uint32_t kb0 = f2tf32(k0v), kb1 = f2tf32(k1v);
                *(uint2*)&g_Kb[off] = make_uint2(kb0, kb1);
                *(uint2*)&g_Ks[off] = make_uint2(f2tf32(k0v - __uint_as_float(kb0)),
                                                 f2tf32(k1v - __uint_as_float(kb1)));
            }
        }
    }
    // V: transposed [b,h,e,s], tf32 bits
    const size_t vbase = ((size_t)b*HH + h) * DH;
    #pragma unroll
    for (int ms = 0; ms < 2; ms++) {
        int r0 = s0 + wm*32 + ms*16 + tg;
        #pragma unroll
        for (int j = 0; j < 2; j++) {
            int c0 = wn*16 + j*8 + tig*2;
            g_Vt[(vbase + c0    )*SS + r0    ] = f2tf32(acc[2][ms][j][0]);
            g_Vt[(vbase + c0 + 1)*SS + r0    ] = f2tf32(acc[2][ms][j][1]);
            g_Vt[(vbase + c0    )*SS + r0 + 8] = f2tf32(acc[2][ms][j][2]);
            g_Vt[(vbase + c0 + 1)*SS + r0 + 8] = f2tf32(acc[2][ms][j][3]);
        }
    }
}

// ---------------------------------------------------------------------------
// Kernel 2: tensor-core causal flash attention, cp.async 2-stage pipeline.
// grid (8, 12, 4); 256 threads (8 warps); block = 128 q-rows, warp = 16 rows.
// QK^T in 3xTF32, PV in tf32. Softmax stats in registers.
// ---------------------------------------------------------------------------
#define PST   68
#define TILEW (64*PST)      // 4352 words per 64-row tile

__global__ __launch_bounds__(256, 1)
void attn_kernel(float* __restrict__ out) {
    extern __shared__ uint32_t smu[];
    // layout: [stage][Kb,Ks,Vt] then Ps(128 rows)
    uint32_t* Ps = smu + 6*TILEW;

    const int mtl = gridDim.x - 1 - blockIdx.x;   // heavy blocks first
    const int h = blockIdx.y, b = blockIdx.z;
    const int tid = threadIdx.x, wid = tid >> 5, lane = tid & 31;
    const int tg = lane >> 2, tig = lane & 3;
    const int m0 = mtl * 128;
    const int ktmax = 2*mtl + 1;
    const size_t bh = ((size_t)b*HH + h) * SS;
    const uint32_t* gqb = g_Qb + bh*DH;
    const uint32_t* gqs = g_Qs + bh*DH;
    const uint32_t* gkb = g_Kb + bh*DH;
    const uint32_t* gks = g_Ks + bh*DH;
    const uint32_t* gvt = g_Vt + ((size_t)b*HH + h) * DH * SS;

    const uint32_t smem_base = (uint32_t)__cvta_generic_to_shared(smu);

    // Q fragments (resident): big + small
    uint32_t qb[8][4], qs[8][4];
    {
        const int r0 = m0 + wid*16 + tg;
        #pragma unroll
        for (int k = 0; k < 8; k++) {
            qb[k][0] = gqb[(size_t)(r0    )*DH + k*8 + tig    ];
            qb[k][1] = gqb[(size_t)(r0 + 8)*DH + k*8 + tig    ];
            qb[k][2] = gqb[(size_t)(r0    )*DH + k*8 + tig + 4];
            qb[k][3] = gqb[(size_t)(r0 + 8)*DH + k*8 + tig + 4];
            qs[k][0] = gqs[(size_t)(r0    )*DH + k*8 + tig    ];
            qs[k][1] = gqs[(size_t)(r0 + 8)*DH + k*8 + tig    ];
            qs[k][2] = gqs[(size_t)(r0    )*DH + k*8 + tig + 4];
            qs[k][3] = gqs[(size_t)(r0 + 8)*DH + k*8 + tig + 4];
        }
    }

    // async tile copy: 4 chunks of 16B per thread per array
    auto copy_tile = [&](int kt, int stage) {
        const uint32_t sb = smem_base + stage * (3*TILEW*4);
        #pragma unroll
        for (int u = 0; u < 4; u++) {
            int idx = tid + u*256;
            int r = idx >> 4, c = idx & 15;
            uint32_t so = r*(PST*4) + c*16;
            cpa16(sb              + so, gkb + (size_t)(kt*64 + r)*DH + c*4);
            cpa16(sb + TILEW*4    + so, gks + (size_t)(kt*64 + r)*DH + c*4);
            cpa16(sb + 2*TILEW*4  + so, gvt + (size_t)r*SS + kt*64 + c*4);
        }
        cpa_commit();
    };

    float o[8][4];
    #pragma unroll
    for (int j = 0; j < 8; j++)
        #pragma unroll
        for (int i = 0; i < 4; i++) o[j][i] = 0.f;
    float mrow[2] = {-1e30f, -1e30f};
    float lrow[2] = {0.f, 0.f};

    copy_tile(0, 0);

    for (int kt = 0; kt <= ktmax; kt++) {
        if (kt < ktmax) { copy_tile(kt+1, (kt+1)&1); cpa_wait<1>(); }
        else            { cpa_wait<0>(); }
        __syncthreads();

        const uint32_t* Kb = smu + (kt&1)*(3*TILEW);
        const uint32_t* Ks = Kb + TILEW;
        const uint32_t* Vs = Kb + 2*TILEW;

        // warps whose rows all precede this tile skip compute entirely
        const int wrow0 = m0 + wid*16;
        if (kt*64 <= wrow0 + 15) {
            // ---- S = Q K^T (3xTF32) ----
            float c[8][4];
            #pragma unroll
            for (int j = 0; j < 8; j++)
                #pragma unroll
                for (int i = 0; i < 4; i++) c[j][i] = 0.f;

            #pragma unroll
            for (int k = 0; k < 8; k++) {
                #pragma unroll
                for (int j = 0; j < 8; j++) {
                    const int nr = j*8 + tg;
                    uint32_t b0 = Kb[nr*PST + k*8 + tig];
                    uint32_t b1 = Kb[nr*PST + k*8 + tig + 4];
                    uint32_t s0 = Ks[nr*PST + k*8 + tig];
                    uint32_t s1 = Ks[nr*PST + k*8 + tig + 4];
                    mma_tf32(c[j], qb[k][0], qb[k][1], qb[k][2], qb[k][3], b0, b1);
                    mma_tf32(c[j], qs[k][0], qs[k][1], qs[k][2], qs[k][3], b0, b1);
                    mma_tf32(c[j], qb[k][0], qb[k][1], qb[k][2], qb[k][3], s0, s1);
                }
            }

            const float sc = 0.125f;
            #pragma unroll
            for (int j = 0; j < 8; j++)
                #pragma unroll
                for (int i = 0; i < 4; i++) c[j][i] *= sc;

            // causal mask if tile reaches past warp's first row
            if (kt*64 + 63 > wrow0) {
                const int rl0 = wrow0 + tg, rl1 = rl0 + 8;
                #pragma unroll
                for (int j = 0; j < 8; j++) {
                    int c0 = kt*64 + j*8 + 2*tig, c1 = c0 + 1;
                    if (c0 > rl0) c[j][0] = -1e30f;
                    if (c1 > rl0) c[j][1] = -1e30f;
                    if (c0 > rl1) c[j][2] = -1e30f;
                    if (c1 > rl1) c[j][3] = -1e30f;
                }
            }

            // ---- online softmax (register stats) ----
            float alpha[2];
            #pragma unroll
            for (int h2 = 0; h2 < 2; h2++) {
                float mx = -1e30f;
                #pragma unroll
                for (int j = 0; j < 8; j++) {
                    mx = fmaxf(mx, c[j][h2*2]);
                    mx = fmaxf(mx, c[j][h2*2 + 1]);
                }
                mx = fmaxf(mx, __shfl_xor_sync(0xffffffffu, mx, 1));
                mx = fmaxf(mx, __shfl_xor_sync(0xffffffffu, mx, 2));
                float mnew = fmaxf(mrow[h2], mx);
                float sum = 0.f;
                #pragma unroll
                for (int j = 0; j < 8; j++) {
                    float p0 = __expf(c[j][h2*2]     - mnew);
                    float p1 = __expf(c[j][h2*2 + 1] - mnew);
                    c[j][h2*2]     = p0;
                    c[j][h2*2 + 1] = p1;
                    sum += p0 + p1;
                }
                sum += __shfl_xor_sync(0xffffffffu, sum, 1);
                sum += __shfl_xor_sync(0xffffffffu, sum, 2);
                alpha[h2] = __expf(mrow[h2] - mnew);
                mrow[h2] = mnew;
                lrow[h2] = lrow[h2]*alpha[h2] + sum;
            }

            // ---- write P (tf32, warp-private rows) + rescale O ----
            {
                const int rb0 = (wid*16 + tg)*PST, rb1 = rb0 + 8*PST;
                #pragma unroll
                for (int j = 0; j < 8; j++) {
                    int cc = j*8 + 2*tig;
                    *(uint2*)&Ps[rb0 + cc] = make_uint2(f2tf32(c[j][0]), f2tf32(c[j][1]));
                    *(uint2*)&Ps[rb1 + cc] = make_uint2(f2tf32(c[j][2]), f2tf32(c[j][3]));
                }
            }
            #pragma unroll
            for (int j = 0; j < 8; j++) {
                o[j][0] *= alpha[0]; o[j][1] *= alpha[0];
                o[j][2] *= alpha[1]; o[j][3] *= alpha[1];
            }
            __syncwarp();

            // ---- O += P V ----
            #pragma unroll
            for (int k = 0; k < 8; k++) {
                uint32_t p0 = Ps[(wid*16 + tg    )*PST + k*8 + tig];
                uint32_t p1 = Ps[(wid*16 + tg + 8)*PST + k*8 + tig];
                uint32_t p2 = Ps[(wid*16 + tg    )*PST + k*8 + tig + 4];
                uint32_t p3 = Ps[(wid*16 + tg + 8)*PST + k*8 + tig + 4];
                #pragma unroll
                for (int j = 0; j < 8; j++) {
                    uint32_t v0 = Vs[(j*8 + tg)*PST + k*8 + tig];
                    uint32_t v1 = Vs[(j*8 + tg)*PST + k*8 + tig + 4];
                    mma_tf32(o[j], p0, p1, p2, p3, v0, v1);
                }
            }
        }
        __syncthreads();   // all warps done with stage (kt&1) before it is refilled
    }

    // ---- epilogue ----
    const float inv0 = 1.f / lrow[0], inv1 = 1.f / lrow[1];
    const int r0 = m0 + wid*16 + tg;
    #pragma unroll
    for (int j = 0; j < 8; j++) {
        int col = h*DH + j*8 + 2*tig;
        *(float2*)&out[((size_t)b*SS + r0    )*(HH*DH) + col] =
            make_float2(o[j][0]*inv0, o[j][1]*inv0);
        *(float2*)&out[((size_t)b*SS + r0 + 8)*(HH*DH) + col] =
            make_float2(o[j][2]*inv1, o[j][3]*inv1);
    }
}

// ---------------------------------------------------------------------------
extern "C" void kernel_launch(void* const* d_in, const int* in_sizes, int n_in,
                              void* d_out, int out_size) {
    const float* x  = (const float*)d_in[0];
    const float* Wq = (const float*)d_in[1];
    const float* Wk = (const float*)d_in[2];
    const float* Wv = (const float*)d_in[3];
    float* out = (float*)d_out;

    const int proj_smem = (2*XW + 2*WW) * (int)sizeof(uint32_t);   // 92,160 B
    cudaFuncSetAttribute(qkv_proj_kernel, cudaFuncAttributeMaxDynamicSharedMemorySize,
                         proj_smem);
    qkv_proj_kernel<<<dim3((BB*SS)/128, HH), 512, proj_smem>>>(x, Wq, Wk, Wv);

    const int attn_smem = (6*TILEW + 128*PST) * (int)sizeof(uint32_t);  // 139,264 B
    cudaFuncSetAttribute(attn_kernel, cudaFuncAttributeMaxDynamicSharedMemorySize,
                         attn_smem);
    attn_kernel<<<dim3(SS/128, HH, BB), 256, attn_smem>>>(out);
}

// round 5
// speedup vs baseline: 1.1020x; 1.1020x over previous
#include <cuda_runtime.h>
#include <cstdint>

// Problem constants
#define BB   4
#define SS   1024
#define DIN  768
#define HH   12
#define DH   64

// Scratch (device globals; no allocs allowed).
// g_Qf : fp32 [b,h,s,e]
// g_Kf : per (b,h): s(1024) x 32 units x 16B. unit(s,k8,tig) = {tf32 kb(c), kb(c+4), ks(c), ks(c+4)}, c=k8*8+tig
// g_Vf : per (b,h): e(64) x 128 ks8 x 4 tig units x 8B. unit = {tf32 v(s=ks8*8+tig), v(s+4)}
__device__ float    g_Qf[BB*HH*SS*DH];
__device__ uint32_t g_Kf[(size_t)BB*HH*SS*128];
__device__ uint32_t g_Vf[(size_t)BB*HH*DH*SS];

// ---------------------------------------------------------------------------
// helpers
// ---------------------------------------------------------------------------
__device__ __forceinline__ uint32_t f2tf32(float f) {
    uint32_t r;
    asm("cvt.rna.tf32.f32 %0, %1;" : "=r"(r) : "f"(f));
    return r;
}

__device__ __forceinline__ void mma_tf32(float c[4],
                                         uint32_t a0, uint32_t a1, uint32_t a2, uint32_t a3,
                                         uint32_t b0, uint32_t b1) {
    asm volatile(
        "mma.sync.aligned.m16n8k8.row.col.f32.tf32.tf32.f32 "
        "{%0,%1,%2,%3}, {%4,%5,%6,%7}, {%8,%9}, {%0,%1,%2,%3};"
        : "+f"(c[0]), "+f"(c[1]), "+f"(c[2]), "+f"(c[3])
        : "r"(a0), "r"(a1), "r"(a2), "r"(a3), "r"(b0), "r"(b1));
}

__device__ __forceinline__ void cpa16(uint32_t smem_addr, const void* gptr) {
    asm volatile("cp.async.cg.shared.global [%0], [%1], 16;"
                 :: "r"(smem_addr), "l"(gptr));
}
__device__ __forceinline__ void cpa_commit() {
    asm volatile("cp.async.commit_group;");
}
template <int N>
__device__ __forceinline__ void cpa_wait() {
    asm volatile("cp.async.wait_group %0;" :: "n"(N));
}

// ---------------------------------------------------------------------------
// Kernel 1: fused QKV projection via tf32 mma, double-buffered smem.
// grid (4096/128, 12); 512 threads (16 warps: 4 in M x 4 in N).
// Epilogue: Q fp32 direct; K/V bounce through smem -> linear wide stores in
// the fragment-unit layouts the attention kernel consumes.
// ---------------------------------------------------------------------------
#define XSTR 36
#define WSTR 72
#define XW   (128*XSTR)      // words per X stage
#define WW   (3*32*WSTR)     // words per W stage

__global__ __launch_bounds__(512, 1)
void qkv_proj_kernel(const float* __restrict__ x,
                     const float* __restrict__ Wq,
                     const float* __restrict__ Wk,
                     const float* __restrict__ Wv) {
    extern __shared__ uint32_t psm[];
    uint32_t* Xs[2] = { psm, psm + XW };
    uint32_t* Ws[2] = { psm + 2*XW, psm + 2*XW + WW };

    const int tid = threadIdx.x;
    const int wid = tid >> 5, lane = tid & 31;
    const int tg = lane >> 2, tig = lane & 3;
    const int wm = wid >> 2, wn = wid & 3;
    const int h = blockIdx.y;
    const int rowblk = blockIdx.x * 128;

    const float* xb = x + (size_t)rowblk * DIN;
    const float* wp[3] = { Wq + (size_t)h * DIN * DH,
                           Wk + (size_t)h * DIN * DH,
                           Wv + (size_t)h * DIN * DH };

    float acc[3][2][2][4];
    #pragma unroll
    for (int m = 0; m < 3; m++)
        #pragma unroll
        for (int i = 0; i < 2; i++)
            #pragma unroll
            for (int j = 0; j < 2; j++)
                #pragma unroll
                for (int r = 0; r < 4; r++) acc[m][i][j][r] = 0.f;

    const int wk_ = tid >> 4, wn4 = (tid & 15) * 4;

    float4 xv[2], wv[3];
    #pragma unroll
    for (int it = 0; it < 2; it++) {
        int idx = tid + it*512, row = idx >> 3, c4 = (idx & 7) * 4;
        xv[it] = *(const float4*)&xb[(size_t)row*DIN + c4];
    }
    #pragma unroll
    for (int m = 0; m < 3; m++)
        wv[m] = *(const float4*)&wp[m][(size_t)wk_*DH + wn4];

    for (int kc = 0; kc < DIN/32; kc++) {
        const int buf = kc & 1;
        #pragma unroll
        for (int it = 0; it < 2; it++) {
            int idx = tid + it*512, row = idx >> 3, c4 = (idx & 7) * 4;
            *(uint4*)&Xs[buf][row*XSTR + c4] =
                make_uint4(f2tf32(xv[it].x), f2tf32(xv[it].y),
                           f2tf32(xv[it].z), f2tf32(xv[it].w));
        }
        #pragma unroll
        for (int m = 0; m < 3; m++) {
            *(uint4*)&Ws[buf][m*32*WSTR + wk_*WSTR + wn4] =
                make_uint4(f2tf32(wv[m].x), f2tf32(wv[m].y),
                           f2tf32(wv[m].z), f2tf32(wv[m].w));
        }
        __syncthreads();

        if (kc + 1 < DIN/32) {
            int k0n = (kc + 1) * 32;
            #pragma unroll
            for (int it = 0; it < 2; it++) {
                int idx = tid + it*512, row = idx >> 3, c4 = (idx & 7) * 4;
                xv[it] = *(const float4*)&xb[(size_t)row*DIN + k0n + c4];
            }
            #pragma unroll
            for (int m = 0; m < 3; m++)
                wv[m] = *(const float4*)&wp[m][(size_t)(k0n + wk_)*DH + wn4];
        }

        #pragma unroll
        for (int kk = 0; kk < 4; kk++) {
            const int k0 = kk * 8;
            uint32_t a[2][4];
            #pragma unroll
            for (int ms = 0; ms < 2; ms++) {
                int r0 = wm*32 + ms*16 + tg;
                a[ms][0] = Xs[buf][(r0    )*XSTR + k0 + tig    ];
                a[ms][1] = Xs[buf][(r0 + 8)*XSTR + k0 + tig    ];
                a[ms][2] = Xs[buf][(r0    )*XSTR + k0 + tig + 4];
                a[ms][3] = Xs[buf][(r0 + 8)*XSTR + k0 + tig + 4];
            }
            #pragma unroll
            for (int m = 0; m < 3; m++) {
                #pragma unroll
                for (int j = 0; j < 2; j++) {
                    int n0 = wn*16 + j*8 + tg;
                    uint32_t b0 = Ws[buf][m*32*WSTR + (k0 + tig    )*WSTR + n0];
                    uint32_t b1 = Ws[buf][m*32*WSTR + (k0 + tig + 4)*WSTR + n0];
                    #pragma unroll
                    for (int ms = 0; ms < 2; ms++)
                        mma_tf32(acc[m][ms][j], a[ms][0], a[ms][1], a[ms][2], a[ms][3], b0, b1);
                }
            }
        }
    }

    // ------------------- Epilogue -------------------
    const int b = rowblk >> 10;
    const int s0 = rowblk & 1023;
    const size_t base = (((size_t)b*HH + h)*SS);

    // Q: fp32 direct
    #pragma unroll
    for (int ms = 0; ms < 2; ms++) {
        int r0 = s0 + wm*32 + ms*16 + tg;
        #pragma unroll
        for (int j = 0; j < 2; j++) {
            int c0 = wn*16 + j*8 + tig*2;
            #pragma unroll
            for (int half = 0; half < 2; half++) {
                *(float2*)&g_Qf[(base + r0 + half*8)*DH + c0] =
                    make_float2(acc[0][ms][j][half*2], acc[0][ms][j][half*2+1]);
            }
        }
    }

    // K, V: bounce through smem (fp32, stride 68), then emit wide linear stores.
    __syncthreads();   // everyone done reading Xs/Ws
    float* Ksm = (float*)psm;               // [128][68]
    float* Vsm = (float*)psm + 128*68;      // [128][68]
    #pragma unroll
    for (int ms = 0; ms < 2; ms++) {
        int rl = wm*32 + ms*16 + tg;
        #pragma unroll
        for (int j = 0; j < 2; j++) {
            int c0 = wn*16 + j*8 + tig*2;
            #pragma unroll
            for (int half = 0; half < 2; half++) {
                *(float2*)&Ksm[(rl + half*8)*68 + c0] =
                    make_float2(acc[1][ms][j][half*2], acc[1][ms][j][half*2+1]);
                *(float2*)&Vsm[(rl + half*8)*68 + c0] =
                    make_float2(acc[2][ms][j][half*2], acc[2][ms][j][half*2+1]);
            }
        }
    }
    __syncthreads();

    // Emit Kf: 4096 16B units, linear STG.128
    {
        uint32_t* kf = g_Kf + base*128 + (size_t)s0*128;
        #pragma unroll
        for (int u = 0; u < 8; u++) {
            int idx = tid + u*512;            // 0..4095
            int sl = idx >> 5, un = idx & 31;
            int k8 = un >> 2, tgu = un & 3;
            int c = k8*8 + tgu;
            float f0 = Ksm[sl*68 + c];
            float f1 = Ksm[sl*68 + c + 4];
            uint32_t b0 = f2tf32(f0), b1 = f2tf32(f1);
            uint32_t r0 = f2tf32(f0 - __uint_as_float(b0));
            uint32_t r1 = f2tf32(f1 - __uint_as_float(b1));
            *(uint4*)&kf[(size_t)idx*4] = make_uint4(b0, b1, r0, r1);
        }
    }
    // Emit Vf: 4096 8B units, linear STG.64
    {
        uint32_t* vf = g_Vf + ((size_t)b*HH + h) * (DH*SS);
        #pragma unroll
        for (int u = 0; u < 8; u++) {
            int idx = tid + u*512;            // 0..4095
            int e = idx >> 6, rem = idx & 63;
            int ks8l = rem >> 2, tgu = rem & 3;
            int sl = ks8l*8 + tgu;
            float f0 = Vsm[(sl    )*68 + e];
            float f1 = Vsm[(sl + 4)*68 + e];
            *(uint2*)&vf[(size_t)e*1024 + ((s0 >> 3) + ks8l)*8 + tgu*2] =
                make_uint2(f2tf32(f0), f2tf32(f1));
        }
    }
}

// ---------------------------------------------------------------------------
// Kernel 2: tensor-core causal flash attention.
// grid (16, 12, 4); 128 threads (4 warps, warp = 16 q-rows, block = 64 rows).
// cp.async 2-stage pipeline; fragment-unit smem layouts (XOR swizzled);
// P kept in registers (shfl transpose). 2 CTAs/SM.
// ---------------------------------------------------------------------------
#define STW 12288    // words per stage: Kf 8192 + Vf 4096

__global__ __launch_bounds__(128, 2)
void attn_kernel(float* __restrict__ out) {
    extern __shared__ uint32_t smu[];

    const int mt = gridDim.x - 1 - blockIdx.x;   // heavy blocks first
    const int h = blockIdx.y, b = blockIdx.z;
    const int tid = threadIdx.x, wid = tid >> 5, lane = tid & 31;
    const int tg = lane >> 2, tig = lane & 3;
    const int m0 = mt * 64;
    const size_t bh = ((size_t)b*HH + h) * SS;
    const float*    gqf = g_Qf + bh*DH;
    const uint32_t* gkf = g_Kf + bh*128;
    const uint32_t* gvf = g_Vf + ((size_t)b*HH + h) * (DH*SS);

    const uint32_t smem_base = (uint32_t)__cvta_generic_to_shared(smu);

    // Q fragments: load fp32 once, split big/small tf32 in regs
    uint32_t qb[8][4], qs[8][4];
    {
        const int r0 = m0 + wid*16 + tg;
        #pragma unroll
        for (int k = 0; k < 8; k++) {
            float f[4];
            f[0] = gqf[(size_t)(r0    )*DH + k*8 + tig    ];
            f[1] = gqf[(size_t)(r0 + 8)*DH + k*8 + tig    ];
            f[2] = gqf[(size_t)(r0    )*DH + k*8 + tig + 4];
            f[3] = gqf[(size_t)(r0 + 8)*DH + k*8 + tig + 4];
            #pragma unroll
            for (int i = 0; i < 4; i++) {
                qb[k][i] = f2tf32(f[i]);
                qs[k][i] = f2tf32(f[i] - __uint_as_float(qb[k][i]));
            }
        }
    }

    auto copy_tile = [&](int kt, int stage) {
        const uint32_t sb = smem_base + stage * (STW*4);
        // K: 2048 16B units
        #pragma unroll
        for (int u = 0; u < 16; u++) {
            int idx = tid + u*128;            // 0..2047
            int sl = idx >> 5, un = idx & 31;
            int usw = un ^ ((sl & 7) << 2);
            cpa16(sb + (sl*32 + usw)*16,
                  gkf + ((size_t)(kt*64 + sl)*32 + un)*4);
        }
        // V: 1024 16B chunks (2 adjacent 8B units each)
        #pragma unroll
        for (int u = 0; u < 8; u++) {
            int idx = tid + u*128;            // 0..1023
            int e = idx >> 4, p = idx & 15;
            int un = 2*p;
            int usw = un ^ ((e & 7) << 2);
            cpa16(sb + 8192*4 + (e*32 + usw)*8,
                  gvf + (size_t)e*1024 + (kt*32 + un)*2);
        }
        cpa_commit();
    };

    float o[8][4];
    #pragma unroll
    for (int j = 0; j < 8; j++)
        #pragma unroll
        for (int i = 0; i < 4; i++) o[j][i] = 0.f;
    float mrow[2] = {-1e30f, -1e30f};
    float lrow[2] = {0.f, 0.f};

    copy_tile(0, 0);

    for (int kt = 0; kt <= mt; kt++) {
        if (kt < mt) { copy_tile(kt+1, (kt+1)&1); cpa_wait<1>(); }
        else         { cpa_wait<0>(); }
        __syncthreads();

        const uint32_t* Kst = smu + (kt&1)*STW;
        const uint32_t* Vst = Kst + 8192;

        // ---- S = Q K^T (3xTF32), fragments via one LDS.128 each ----
        float c[8][4];
        #pragma unroll
        for (int j = 0; j < 8; j++)
            #pragma unroll
            for (int i = 0; i < 4; i++) c[j][i] = 0.f;

        #pragma unroll
        for (int k = 0; k < 8; k++) {
            const int usw = (k*4 + tig) ^ (tg << 2);
            #pragma unroll
            for (int j = 0; j < 8; j++) {
                const int nr = j*8 + tg;
                uint4 kf = *(const uint4*)&Kst[(nr*32 + usw)*4];
                mma_tf32(c[j], qb[k][0], qb[k][1], qb[k][2], qb[k][3], kf.x, kf.y);
                mma_tf32(c[j], qs[k][0], qs[k][1], qs[k][2], qs[k][3], kf.x, kf.y);
                mma_tf32(c[j], qb[k][0], qb[k][1], qb[k][2], qb[k][3], kf.z, kf.w);
            }
        }

        const float sc = 0.125f;
        #pragma unroll
        for (int j = 0; j < 8; j++)
            #pragma unroll
            for (int i = 0; i < 4; i++) c[j][i] *= sc;

        if (kt == mt) {       // diagonal tile: causal mask
            const int rl0 = wid*16 + tg, rl1 = rl0 + 8;
            #pragma unroll
            for (int j = 0; j < 8; j++) {
                int c0 = j*8 + 2*tig, c1 = c0 + 1;
                if (c0 > rl0) c[j][0] = -1e30f;
                if (c1 > rl0) c[j][1] = -1e30f;
                if (c0 > rl1) c[j][2] = -1e30f;
                if (c1 > rl1) c[j][3] = -1e30f;
            }
        }

        // ---- online softmax (register stats) ----
        float alpha[2];
        #pragma unroll
        for (int h2 = 0; h2 < 2; h2++) {
            float mx = -1e30f;
            #pragma unroll
            for (int j = 0; j < 8; j++) {
                mx = fmaxf(mx, c[j][h2*2]);
                mx = fmaxf(mx, c[j][h2*2 + 1]);
            }
            mx = fmaxf(mx, __shfl_xor_sync(0xffffffffu, mx, 1));
            mx = fmaxf(mx, __shfl_xor_sync(0xffffffffu, mx, 2));
            float mnew = fmaxf(mrow[h2], mx);
            float sum = 0.f;
            #pragma unroll
            for (int j = 0; j < 8; j++) {
                float p0 = __expf(c[j][h2*2]     - mnew);
                float p1 = __expf(c[j][h2*2 + 1] - mnew);
                c[j][h2*2]     = p0;
                c[j][h2*2 + 1] = p1;
                sum += p0 + p1;
            }
            sum += __shfl_xor_sync(0xffffffffu, sum, 1);
            sum += __shfl_xor_sync(0xffffffffu, sum, 2);
            alpha[h2] = __expf(mrow[h2] - mnew);
            mrow[h2] = mnew;
            lrow[h2] = lrow[h2]*alpha[h2] + sum;
        }

        #pragma unroll
        for (int j = 0; j < 8; j++) {
            o[j][0] *= alpha[0]; o[j][1] *= alpha[0];
            o[j][2] *= alpha[1]; o[j][3] *= alpha[1];
        }

        // ---- O += P V : P transposed C-frag -> A-frag via shfl ----
        const int src0 = (tg << 2) + (tig >> 1);
        const int src1 = src0 + 2;
        const bool odd = (tig & 1);
        #pragma unroll
        for (int k = 0; k < 8; k++) {
            float e0 = __shfl_sync(0xffffffffu, c[k][0], src0);
            float o0 = __shfl_sync(0xffffffffu, c[k][1], src0);
            float e1 = __shfl_sync(0xffffffffu, c[k][2], src0);
            float o1 = __shfl_sync(0xffffffffu, c[k][3], src0);
            float e2 = __shfl_sync(0xffffffffu, c[k][0], src1);
            float o2 = __shfl_sync(0xffffffffu, c[k][1], src1);
            float e3 = __shfl_sync(0xffffffffu, c[k][2], src1);
            float o3 = __shfl_sync(0xffffffffu, c[k][3], src1);
            uint32_t a0 = f2tf32(odd ? o0 : e0);
            uint32_t a1 = f2tf32(odd ? o1 : e1);
            uint32_t a2 = f2tf32(odd ? o2 : e2);
            uint32_t a3 = f2tf32(odd ? o3 : e3);

            const int usw = (k*4 + tig) ^ (tg << 2);
            #pragma unroll
            for (int jn = 0; jn < 8; jn++) {
                const int e = jn*8 + tg;
                uint2 vf = *(const uint2*)&Vst[8192 - 8192 + (e*32 + usw)*2 + 0];
                mma_tf32(o[jn], a0, a1, a2, a3, vf.x, vf.y);
            }
        }
        __syncthreads();   // all warps done with this stage before refill
    }

    // ---- epilogue: normalize + write [B,S,H*DH] ----
    const float inv0 = 1.f / lrow[0], inv1 = 1.f / lrow[1];
    const int r0 = m0 + wid*16 + tg;
    #pragma unroll
    for (int j = 0; j < 8; j++) {
        int col = h*DH + j*8 + 2*tig;
        *(float2*)&out[((size_t)b*SS + r0    )*(HH*DH) + col] =
            make_float2(o[j][0]*inv0, o[j][1]*inv0);
        *(float2*)&out[((size_t)b*SS + r0 + 8)*(HH*DH) + col] =
            make_float2(o[j][2]*inv1, o[j][3]*inv1);
    }
}

// ---------------------------------------------------------------------------
extern "C" void kernel_launch(void* const* d_in, const int* in_sizes, int n_in,
                              void* d_out, int out_size) {
    const float* x  = (const float*)d_in[0];
    const float* Wq = (const float*)d_in[1];
    const float* Wk = (const float*)d_in[2];
    const float* Wv = (const float*)d_in[3];
    float* out = (float*)d_out;

    const int proj_smem = (2*XW + 2*WW) * (int)sizeof(uint32_t);   // 92,160 B
    cudaFuncSetAttribute(qkv_proj_kernel, cudaFuncAttributeMaxDynamicSharedMemorySize,
                         proj_smem);
    qkv_proj_kernel<<<dim3((BB*SS)/128, HH), 512, proj_smem>>>(x, Wq, Wk, Wv);

    const int attn_smem = 2 * STW * (int)sizeof(uint32_t);          // 98,304 B
    cudaFuncSetAttribute(attn_kernel, cudaFuncAttributeMaxDynamicSharedMemorySize,
                         attn_smem);
    attn_kernel<<<dim3(SS/64, HH, BB), 128, attn_smem>>>(out);
}

// round 6
// speedup vs baseline: 1.1597x; 1.0524x over previous
#include <cuda_runtime.h>
#include <cstdint>

// Problem constants
#define BB   4
#define SS   1024
#define DIN  768
#define HH   12
#define DH   64

// Scratch (device globals; no allocs allowed).
// g_Qf : fp32 [b,h,s,e]
// g_Kf : per (b,h): s x 32 units x 8B. unit(s,k8,tgu) = {tf32 k(c), k(c+4)}, c=k8*8+tgu (k8 0..7)
// g_Vf : per (b,h): e(64) x 128 ks8 x 4 tgu units x 8B. unit = {tf32 v(s=ks8*8+tgu), v(s+4)}
__device__ float    g_Qf[BB*HH*SS*DH];
__device__ uint32_t g_Kf[(size_t)BB*HH*SS*DH];
__device__ uint32_t g_Vf[(size_t)BB*HH*DH*SS];

// ---------------------------------------------------------------------------
// helpers
// ---------------------------------------------------------------------------
__device__ __forceinline__ uint32_t f2tf32(float f) {
    uint32_t r;
    asm("cvt.rna.tf32.f32 %0, %1;" : "=r"(r) : "f"(f));
    return r;
}

__device__ __forceinline__ void mma_tf32(float c[4],
                                         uint32_t a0, uint32_t a1, uint32_t a2, uint32_t a3,
                                         uint32_t b0, uint32_t b1) {
    asm volatile(
        "mma.sync.aligned.m16n8k8.row.col.f32.tf32.tf32.f32 "
        "{%0,%1,%2,%3}, {%4,%5,%6,%7}, {%8,%9}, {%0,%1,%2,%3};"
        : "+f"(c[0]), "+f"(c[1]), "+f"(c[2]), "+f"(c[3])
        : "r"(a0), "r"(a1), "r"(a2), "r"(a3), "r"(b0), "r"(b1));
}

__device__ __forceinline__ void cpa16(uint32_t smem_addr, const void* gptr) {
    asm volatile("cp.async.cg.shared.global [%0], [%1], 16;"
                 :: "r"(smem_addr), "l"(gptr));
}
__device__ __forceinline__ void cpa_commit() {
    asm volatile("cp.async.commit_group;");
}
template <int N>
__device__ __forceinline__ void cpa_wait() {
    asm volatile("cp.async.wait_group %0;" :: "n"(N));
}

// ---------------------------------------------------------------------------
// Kernel 1: fused QKV projection via tf32 mma, double-buffered smem.
// grid (4096/64, 12); 256 threads (8 warps: 2 in M x 4 in N); 2 CTAs/SM.
// Block tile: M=64 rows, N=64 per matrix, x3 matrices. Warp: m32 x n16 x3.
// ---------------------------------------------------------------------------
#define XSTR 36
#define WSTR 72
#define XW   (64*XSTR)       // 2304 words per X stage
#define WW   (3*32*WSTR)     // 6912 words per W stage

__global__ __launch_bounds__(256, 2)
void qkv_proj_kernel(const float* __restrict__ x,
                     const float* __restrict__ Wq,
                     const float* __restrict__ Wk,
                     const float* __restrict__ Wv) {
    extern __shared__ uint32_t psm[];
    uint32_t* Xs[2] = { psm, psm + XW };
    uint32_t* Ws[2] = { psm + 2*XW, psm + 2*XW + WW };

    const int tid = threadIdx.x;
    const int wid = tid >> 5, lane = tid & 31;
    const int tg = lane >> 2, tig = lane & 3;
    const int wm = wid >> 2, wn = wid & 3;     // 2 x 4 warps
    const int h = blockIdx.y;
    const int rowblk = blockIdx.x * 64;

    const float* xb = x + (size_t)rowblk * DIN;
    const float* wp[3] = { Wq + (size_t)h * DIN * DH,
                           Wk + (size_t)h * DIN * DH,
                           Wv + (size_t)h * DIN * DH };

    float acc[3][2][2][4];
    #pragma unroll
    for (int m = 0; m < 3; m++)
        #pragma unroll
        for (int i = 0; i < 2; i++)
            #pragma unroll
            for (int j = 0; j < 2; j++)
                #pragma unroll
                for (int r = 0; r < 4; r++) acc[m][i][j][r] = 0.f;

    float4 xv[2], wv[3][2];
    // preload chunk 0
    #pragma unroll
    for (int it = 0; it < 2; it++) {
        int idx = tid + it*256, row = idx >> 3, c4 = (idx & 7) * 4;
        xv[it] = *(const float4*)&xb[(size_t)row*DIN + c4];
    }
    #pragma unroll
    for (int m = 0; m < 3; m++)
        #pragma unroll
        for (int it = 0; it < 2; it++) {
            int idx = tid + it*256, k = idx >> 4, n4 = (idx & 15) * 4;
            wv[m][it] = *(const float4*)&wp[m][(size_t)k*DH + n4];
        }

    for (int kc = 0; kc < DIN/32; kc++) {
        const int buf = kc & 1;
        #pragma unroll
        for (int it = 0; it < 2; it++) {
            int idx = tid + it*256, row = idx >> 3, c4 = (idx & 7) * 4;
            *(uint4*)&Xs[buf][row*XSTR + c4] =
                make_uint4(f2tf32(xv[it].x), f2tf32(xv[it].y),
                           f2tf32(xv[it].z), f2tf32(xv[it].w));
        }
        #pragma unroll
        for (int m = 0; m < 3; m++)
            #pragma unroll
            for (int it = 0; it < 2; it++) {
                int idx = tid + it*256, k = idx >> 4, n4 = (idx & 15) * 4;
                *(uint4*)&Ws[buf][m*32*WSTR + k*WSTR + n4] =
                    make_uint4(f2tf32(wv[m][it].x), f2tf32(wv[m][it].y),
                               f2tf32(wv[m][it].z), f2tf32(wv[m][it].w));
            }
        __syncthreads();

        if (kc + 1 < DIN/32) {
            int k0n = (kc + 1) * 32;
            #pragma unroll
            for (int it = 0; it < 2; it++) {
                int idx = tid + it*256, row = idx >> 3, c4 = (idx & 7) * 4;
                xv[it] = *(const float4*)&xb[(size_t)row*DIN + k0n + c4];
            }
            #pragma unroll
            for (int m = 0; m < 3; m++)
                #pragma unroll
                for (int it = 0; it < 2; it++) {
                    int idx = tid + it*256, k = idx >> 4, n4 = (idx & 15) * 4;
                    wv[m][it] = *(const float4*)&wp[m][(size_t)(k0n + k)*DH + n4];
                }
        }

        #pragma unroll
        for (int kk = 0; kk < 4; kk++) {
            const int k0 = kk * 8;
            uint32_t a[2][4];
            #pragma unroll
            for (int ms = 0; ms < 2; ms++) {
                int r0 = wm*32 + ms*16 + tg;
                a[ms][0] = Xs[buf][(r0    )*XSTR + k0 + tig    ];
                a[ms][1] = Xs[buf][(r0 + 8)*XSTR + k0 + tig    ];
                a[ms][2] = Xs[buf][(r0    )*XSTR + k0 + tig + 4];
                a[ms][3] = Xs[buf][(r0 + 8)*XSTR + k0 + tig + 4];
            }
            #pragma unroll
            for (int m = 0; m < 3; m++) {
                #pragma unroll
                for (int j = 0; j < 2; j++) {
                    int n0 = wn*16 + j*8 + tg;
                    uint32_t b0 = Ws[buf][m*32*WSTR + (k0 + tig    )*WSTR + n0];
                    uint32_t b1 = Ws[buf][m*32*WSTR + (k0 + tig + 4)*WSTR + n0];
                    #pragma unroll
                    for (int ms = 0; ms < 2; ms++)
                        mma_tf32(acc[m][ms][j], a[ms][0], a[ms][1], a[ms][2], a[ms][3], b0, b1);
                }
            }
        }
    }

    // ------------------- Epilogue -------------------
    const int b = rowblk >> 10;
    const int s0 = rowblk & 1023;
    const size_t base = (((size_t)b*HH + h)*SS);

    // Q: fp32 direct
    #pragma unroll
    for (int ms = 0; ms < 2; ms++) {
        int r0 = s0 + wm*32 + ms*16 + tg;
        #pragma unroll
        for (int j = 0; j < 2; j++) {
            int c0 = wn*16 + j*8 + tig*2;
            #pragma unroll
            for (int half = 0; half < 2; half++) {
                *(float2*)&g_Qf[(base + r0 + half*8)*DH + c0] =
                    make_float2(acc[0][ms][j][half*2], acc[0][ms][j][half*2+1]);
            }
        }
    }

    // K, V: bounce through smem (fp32, stride 68), emit unit layouts linearly.
    __syncthreads();
    float* Ksm = (float*)psm;               // [64][68]
    float* Vsm = (float*)psm + 64*68;       // [64][68]
    #pragma unroll
    for (int ms = 0; ms < 2; ms++) {
        int rl = wm*32 + ms*16 + tg;
        #pragma unroll
        for (int j = 0; j < 2; j++) {
            int c0 = wn*16 + j*8 + tig*2;
            #pragma unroll
            for (int half = 0; half < 2; half++) {
                *(float2*)&Ksm[(rl + half*8)*68 + c0] =
                    make_float2(acc[1][ms][j][half*2], acc[1][ms][j][half*2+1]);
                *(float2*)&Vsm[(rl + half*8)*68 + c0] =
                    make_float2(acc[2][ms][j][half*2], acc[2][ms][j][half*2+1]);
            }
        }
    }
    __syncthreads();

    // Kf: 2048 8B units {k(c), k(c+4)}, linear stores
    {
        uint32_t* kf = g_Kf + (base + s0)*DH;
        #pragma unroll
        for (int u = 0; u < 8; u++) {
            int idx = tid + u*256;            // 0..2047
            int sl = idx >> 5, un = idx & 31;
            int k8 = un >> 2, tgu = un & 3;
            int c = k8*8 + tgu;
            float f0 = Ksm[sl*68 + c];
            float f1 = Ksm[sl*68 + c + 4];
            *(uint2*)&kf[(size_t)sl*64 + un*2] = make_uint2(f2tf32(f0), f2tf32(f1));
        }
    }
    // Vf: 2048 8B units {v(s), v(s+4)}
    {
        uint32_t* vf = g_Vf + ((size_t)b*HH + h) * (DH*SS);
        #pragma unroll
        for (int u = 0; u < 8; u++) {
            int idx = tid + u*256;            // 0..2047
            int e = idx >> 5, rem = idx & 31;
            int ks8l = rem >> 2, tgu = rem & 3;
            int sl = ks8l*8 + tgu;
            float f0 = Vsm[(sl    )*68 + e];
            float f1 = Vsm[(sl + 4)*68 + e];
            *(uint2*)&vf[(size_t)e*1024 + ((s0 >> 3) + ks8l)*8 + tgu*2] =
                make_uint2(f2tf32(f0), f2tf32(f1));
        }
    }
}

// ---------------------------------------------------------------------------
// Kernel 2: tensor-core causal flash attention.
// grid (16, 12, 4); 128 threads (4 warps, warp = 16 q-rows, block = 64 rows).
// cp.async 2-stage pipeline; K plain tf32 (2-mma QK: qb*k + qs*k);
// P in registers (shfl transpose). 2 CTAs/SM. smem 64KB.
// ---------------------------------------------------------------------------
#define STW 8192     // words per stage: K 4096 + V 4096

__global__ __launch_bounds__(128, 2)
void attn_kernel(float* __restrict__ out) {
    extern __shared__ uint32_t smu[];

    const int mt = gridDim.x - 1 - blockIdx.x;   // heavy blocks first
    const int h = blockIdx.y, b = blockIdx.z;
    const int tid = threadIdx.x, wid = tid >> 5, lane = tid & 31;
    const int tg = lane >> 2, tig = lane & 3;
    const int m0 = mt * 64;
    const size_t bh = ((size_t)b*HH + h) * SS;
    const float*    gqf = g_Qf + bh*DH;
    const uint32_t* gkf = g_Kf + bh*DH;
    const uint32_t* gvf = g_Vf + ((size_t)b*HH + h) * (DH*SS);

    const uint32_t smem_base = (uint32_t)__cvta_generic_to_shared(smu);

    // Q fragments: fp32 load, split big/small tf32 in regs
    uint32_t qb[8][4], qs[8][4];
    {
        const int r0 = m0 + wid*16 + tg;
        #pragma unroll
        for (int k = 0; k < 8; k++) {
            float f[4];
            f[0] = gqf[(size_t)(r0    )*DH + k*8 + tig    ];
            f[1] = gqf[(size_t)(r0 + 8)*DH + k*8 + tig    ];
            f[2] = gqf[(size_t)(r0    )*DH + k*8 + tig + 4];
            f[3] = gqf[(size_t)(r0 + 8)*DH + k*8 + tig + 4];
            #pragma unroll
            for (int i = 0; i < 4; i++) {
                qb[k][i] = f2tf32(f[i]);
                qs[k][i] = f2tf32(f[i] - __uint_as_float(qb[k][i]));
            }
        }
    }

    auto copy_tile = [&](int kt, int stage) {
        const uint32_t sb = smem_base + stage * (STW*4);
        // K: 1024 16B chunks; swizzle chunk index by row
        #pragma unroll
        for (int u = 0; u < 8; u++) {
            int idx = tid + u*128;            // 0..1023
            int s = idx >> 4, cc = idx & 15;
            int ccs = cc ^ ((s & 7) << 1);
            cpa16(sb + s*256 + ccs*16,
                  gkf + ((size_t)(kt*64 + s)*64 + cc*4));
        }
        // V: 1024 16B chunks
        #pragma unroll
        for (int u = 0; u < 8; u++) {
            int idx = tid + u*128;            // 0..1023
            int e = idx >> 4, p = idx & 15;
            int un = 2*p;
            int usw = un ^ ((e & 7) << 2);
            cpa16(sb + 4096*4 + (e*32 + usw)*8,
                  gvf + (size_t)e*1024 + (kt*32 + un)*2);
        }
        cpa_commit();
    };

    float o[8][4];
    #pragma unroll
    for (int j = 0; j < 8; j++)
        #pragma unroll
        for (int i = 0; i < 4; i++) o[j][i] = 0.f;
    float mrow[2] = {-1e30f, -1e30f};
    float lrow[2] = {0.f, 0.f};

    copy_tile(0, 0);

    for (int kt = 0; kt <= mt; kt++) {
        if (kt < mt) { copy_tile(kt+1, (kt+1)&1); cpa_wait<1>(); }
        else         { cpa_wait<0>(); }
        __syncthreads();

        const uint32_t* Kst = smu + (kt&1)*STW;
        const uint32_t* Vst = Kst + 4096;

        // ---- S = Q K^T (2 mma: qb*k + qs*k), K frag = one LDS.64 ----
        float c[8][4];
        #pragma unroll
        for (int j = 0; j < 8; j++)
            #pragma unroll
            for (int i = 0; i < 4; i++) c[j][i] = 0.f;

        #pragma unroll
        for (int k = 0; k < 8; k++) {
            const int usw = (k*4 + tig) ^ (tg << 2);
            #pragma unroll
            for (int j = 0; j < 8; j++) {
                const int nr = j*8 + tg;
                uint2 kf = *(const uint2*)&Kst[nr*64 + usw*2];
                mma_tf32(c[j], qb[k][0], qb[k][1], qb[k][2], qb[k][3], kf.x, kf.y);
                mma_tf32(c[j], qs[k][0], qs[k][1], qs[k][2], qs[k][3], kf.x, kf.y);
            }
        }

        const float sc = 0.125f;
        #pragma unroll
        for (int j = 0; j < 8; j++)
            #pragma unroll
            for (int i = 0; i < 4; i++) c[j][i] *= sc;

        if (kt == mt) {       // diagonal tile: causal mask
            const int rl0 = wid*16 + tg, rl1 = rl0 + 8;
            #pragma unroll
            for (int j = 0; j < 8; j++) {
                int c0 = j*8 + 2*tig, c1 = c0 + 1;
                if (c0 > rl0) c[j][0] = -1e30f;
                if (c1 > rl0) c[j][1] = -1e30f;
                if (c0 > rl1) c[j][2] = -1e30f;
                if (c1 > rl1) c[j][3] = -1e30f;
            }
        }

        // ---- online softmax (register stats) ----
        float alpha[2];
        #pragma unroll
        for (int h2 = 0; h2 < 2; h2++) {
            float mx = -1e30f;
            #pragma unroll
            for (int j = 0; j < 8; j++) {
                mx = fmaxf(mx, c[j][h2*2]);
                mx = fmaxf(mx, c[j][h2*2 + 1]);
            }
            mx = fmaxf(mx, __shfl_xor_sync(0xffffffffu, mx, 1));
            mx = fmaxf(mx, __shfl_xor_sync(0xffffffffu, mx, 2));
            float mnew = fmaxf(mrow[h2], mx);
            float sum = 0.f;
            #pragma unroll
            for (int j = 0; j < 8; j++) {
                float p0 = __expf(c[j][h2*2]     - mnew);
                float p1 = __expf(c[j][h2*2 + 1] - mnew);
                c[j][h2*2]     = p0;
                c[j][h2*2 + 1] = p1;
                sum += p0 + p1;
            }
            sum += __shfl_xor_sync(0xffffffffu, sum, 1);
            sum += __shfl_xor_sync(0xffffffffu, sum, 2);
            alpha[h2] = __expf(mrow[h2] - mnew);
            mrow[h2] = mnew;
            lrow[h2] = lrow[h2]*alpha[h2] + sum;
        }

        #pragma unroll
        for (int j = 0; j < 8; j++) {
            o[j][0] *= alpha[0]; o[j][1] *= alpha[0];
            o[j][2] *= alpha[1]; o[j][3] *= alpha[1];
        }

        // ---- O += P V : P transposed C-frag -> A-frag via shfl ----
        const int src0 = (tg << 2) + (tig >> 1);
        const int src1 = src0 + 2;
        const bool odd = (tig & 1);
        #pragma unroll
        for (int k = 0; k < 8; k++) {
            float e0 = __shfl_sync(0xffffffffu, c[k][0], src0);
            float o0 = __shfl_sync(0xffffffffu, c[k][1], src0);
            float e1 = __shfl_sync(0xffffffffu, c[k][2], src0);
            float o1 = __shfl_sync(0xffffffffu, c[k][3], src0);
            float e2 = __shfl_sync(0xffffffffu, c[k][0], src1);
            float o2 = __shfl_sync(0xffffffffu, c[k][1], src1);
            float e3 = __shfl_sync(0xffffffffu, c[k][2], src1);
            float o3 = __shfl_sync(0xffffffffu, c[k][3], src1);
            uint32_t a0 = f2tf32(odd ? o0 : e0);
            uint32_t a1 = f2tf32(odd ? o1 : e1);
            uint32_t a2 = f2tf32(odd ? o2 : e2);
            uint32_t a3 = f2tf32(odd ? o3 : e3);

            const int usw = (k*4 + tig) ^ (tg << 2);
            #pragma unroll
            for (int jn = 0; jn < 8; jn++) {
                const int e = jn*8 + tg;
                uint2 vf = *(const uint2*)&Vst[(e*32 + usw)*2];
                mma_tf32(o[jn], a0, a1, a2, a3, vf.x, vf.y);
            }
        }
        __syncthreads();   // all warps done with this stage before refill
    }

    // ---- epilogue: normalize + write [B,S,H*DH] ----
    const float inv0 = 1.f / lrow[0], inv1 = 1.f / lrow[1];
    const int r0 = m0 + wid*16 + tg;
    #pragma unroll
    for (int j = 0; j < 8; j++) {
        int col = h*DH + j*8 + 2*tig;
        *(float2*)&out[((size_t)b*SS + r0    )*(HH*DH) + col] =
            make_float2(o[j][0]*inv0, o[j][1]*inv0);
        *(float2*)&out[((size_t)b*SS + r0 + 8)*(HH*DH) + col] =
            make_float2(o[j][2]*inv1, o[j][3]*inv1);
    }
}

// ---------------------------------------------------------------------------
extern "C" void kernel_launch(void* const* d_in, const int* in_sizes, int n_in,
                              void* d_out, int out_size) {
    const float* x  = (const float*)d_in[0];
    const float* Wq = (const float*)d_in[1];
    const float* Wk = (const float*)d_in[2];
    const float* Wv = (const float*)d_in[3];
    float* out = (float*)d_out;

    const int proj_smem = (2*XW + 2*WW) * (int)sizeof(uint32_t);   // 73,728 B
    cudaFuncSetAttribute(qkv_proj_kernel, cudaFuncAttributeMaxDynamicSharedMemorySize,
                         proj_smem);
    qkv_proj_kernel<<<dim3((BB*SS)/64, HH), 256, proj_smem>>>(x, Wq, Wk, Wv);

    const int attn_smem = 2 * STW * (int)sizeof(uint32_t);          // 65,536 B
    cudaFuncSetAttribute(attn_kernel, cudaFuncAttributeMaxDynamicSharedMemorySize,
                         attn_smem);
    attn_kernel<<<dim3(SS/64, HH, BB), 128, attn_smem>>>(out);
}

// round 7
// speedup vs baseline: 1.3351x; 1.1512x over previous
#include <cuda_runtime.h>
#include <cstdint>

// Problem constants
#define BB   4
#define SS   1024
#define DIN  768
#define HH   12
#define DH   64
#define WWRD (HH*DIN*DH)     // words per weight matrix (589824)

// Scratch (device globals; no allocs allowed).
__device__ __align__(16) uint32_t g_Xr[BB*SS*DIN];      // x pre-rounded to tf32 grid
__device__ __align__(16) uint32_t g_Wr[3*WWRD];         // Wq|Wk|Wv pre-rounded
__device__ __align__(16) float    g_Qf[BB*HH*SS*DH];    // Q fp32 [b,h,s,e]
__device__ __align__(16) uint32_t g_Kf[(size_t)BB*HH*SS*DH];  // K tf32 frag units
__device__ __align__(16) uint32_t g_Vf[(size_t)BB*HH*DH*SS];  // V tf32 frag units

// ---------------------------------------------------------------------------
// helpers
// ---------------------------------------------------------------------------
__device__ __forceinline__ uint32_t f2tf32(float f) {
    uint32_t r;
    asm("cvt.rna.tf32.f32 %0, %1;" : "=r"(r) : "f"(f));
    return r;
}

__device__ __forceinline__ void mma_tf32(float c[4],
                                         uint32_t a0, uint32_t a1, uint32_t a2, uint32_t a3,
                                         uint32_t b0, uint32_t b1) {
    asm volatile(
        "mma.sync.aligned.m16n8k8.row.col.f32.tf32.tf32.f32 "
        "{%0,%1,%2,%3}, {%4,%5,%6,%7}, {%8,%9}, {%0,%1,%2,%3};"
        : "+f"(c[0]), "+f"(c[1]), "+f"(c[2]), "+f"(c[3])
        : "r"(a0), "r"(a1), "r"(a2), "r"(a3), "r"(b0), "r"(b1));
}

__device__ __forceinline__ void cpa16(uint32_t smem_addr, const void* gptr) {
    asm volatile("cp.async.cg.shared.global [%0], [%1], 16;"
                 :: "r"(smem_addr), "l"(gptr));
}
__device__ __forceinline__ void cpa_commit() {
    asm volatile("cp.async.commit_group;");
}
template <int N>
__device__ __forceinline__ void cpa_wait() {
    asm volatile("cp.async.wait_group %0;" :: "n"(N));
}

// ---------------------------------------------------------------------------
// Kernel 0: pre-round x and W onto the tf32 grid (bits + 0x1000; the mma
// truncates low 13 bits, so net effect == cvt.rna.tf32).
// ---------------------------------------------------------------------------
#define XC (BB*SS*DIN/4)     // uint4 chunks of x
#define WC (WWRD/4)          // uint4 chunks per W matrix

__global__ __launch_bounds__(256)
void round_kernel(const uint4* __restrict__ x, const uint4* __restrict__ wq,
                  const uint4* __restrict__ wk, const uint4* __restrict__ wv) {
    const int stride = gridDim.x * blockDim.x;
    for (int i = blockIdx.x*blockDim.x + threadIdx.x; i < XC + 3*WC; i += stride) {
        uint4 v; uint4* dst;
        if (i < XC) {
            v = x[i];
            dst = (uint4*)g_Xr + i;
        } else {
            int j = i - XC;
            int m = j / WC, r = j - m*WC;
            const uint4* src = (m == 0) ? wq : (m == 1) ? wk : wv;
            v = src[r];
            dst = (uint4*)g_Wr + j;
        }
        v.x += 0x1000u; v.y += 0x1000u; v.z += 0x1000u; v.w += 0x1000u;
        *dst = v;
    }
}

// ---------------------------------------------------------------------------
// Kernel 1: fused QKV projection, zero-conversion cp.async tf32 GEMM.
// grid (4096/128, 12); 512 threads (16 warps: 4m x 4n). 3-stage pipeline.
// Block tile: M=128, N=64 per matrix x3. Warp tile m32 x n16 x3.
// ---------------------------------------------------------------------------
#define XSTR 36
#define WSTR 72
#define PXW  (128*XSTR)      // 4608 words: X part of a stage
#define PSTG (PXW + 3*32*WSTR)   // 11520 words per stage
#define PNC  (DIN/32)        // 24 k-chunks

__global__ __launch_bounds__(512, 1)
void qkv_proj_kernel() {
    extern __shared__ uint32_t psm[];

    const int tid = threadIdx.x;
    const int wid = tid >> 5, lane = tid & 31;
    const int tg = lane >> 2, tig = lane & 3;
    const int wm = wid >> 2, wn = wid & 3;
    const int h = blockIdx.y;
    const int rowblk = blockIdx.x * 128;

    const uint32_t* xr = g_Xr + (size_t)rowblk * DIN;
    const uint32_t* wb = g_Wr + (size_t)h * DIN * DH;   // + m*WWRD per matrix

    const uint32_t smem_base = (uint32_t)__cvta_generic_to_shared(psm);

    float acc[3][2][2][4];
    #pragma unroll
    for (int m = 0; m < 3; m++)
        #pragma unroll
        for (int i = 0; i < 2; i++)
            #pragma unroll
            for (int j = 0; j < 2; j++)
                #pragma unroll
                for (int r = 0; r < 4; r++) acc[m][i][j][r] = 0.f;

    auto copy_chunk = [&](int kc, int stage) {
        const uint32_t sb = smem_base + stage * (PSTG*4);
        // X: 1024 16B chunks (128 rows x 8)
        #pragma unroll
        for (int u = 0; u < 2; u++) {
            int idx = tid + u*512, r = idx >> 3, c4 = (idx & 7) * 4;
            cpa16(sb + (r*XSTR + c4)*4, xr + (size_t)r*DIN + kc*32 + c4);
        }
        // W: 1536 16B chunks (3 mats x 32 k x 16)
        #pragma unroll
        for (int u = 0; u < 3; u++) {
            int idx = tid + u*512;
            int m = idx >> 9, rem = idx & 511;
            int k = rem >> 4, n4 = (rem & 15) * 4;
            cpa16(sb + (PXW + m*(32*WSTR) + k*WSTR + n4)*4,
                  wb + (size_t)m*WWRD + (size_t)(kc*32 + k)*DH + n4);
        }
        cpa_commit();
    };

    copy_chunk(0, 0);
    copy_chunk(1, 1);

    for (int kc = 0; kc < PNC; kc++) {
        if (kc == PNC-1) cpa_wait<0>(); else cpa_wait<1>();
        __syncthreads();
        if (kc + 2 < PNC) copy_chunk(kc + 2, (kc + 2) % 3);

        const uint32_t* Xs = psm + (kc % 3) * PSTG;
        const uint32_t* Ws = Xs + PXW;

        #pragma unroll
        for (int kk = 0; kk < 4; kk++) {
            const int k0 = kk * 8;
            uint32_t a[2][4];
            #pragma unroll
            for (int ms = 0; ms < 2; ms++) {
                int r0 = wm*32 + ms*16 + tg;
                a[ms][0] = Xs[(r0    )*XSTR + k0 + tig    ];
                a[ms][1] = Xs[(r0 + 8)*XSTR + k0 + tig    ];
                a[ms][2] = Xs[(r0    )*XSTR + k0 + tig + 4];
                a[ms][3] = Xs[(r0 + 8)*XSTR + k0 + tig + 4];
            }
            #pragma unroll
            for (int m = 0; m < 3; m++) {
                #pragma unroll
                for (int j = 0; j < 2; j++) {
                    int n0 = wn*16 + j*8 + tg;
                    uint32_t b0 = Ws[m*(32*WSTR) + (k0 + tig    )*WSTR + n0];
                    uint32_t b1 = Ws[m*(32*WSTR) + (k0 + tig + 4)*WSTR + n0];
                    #pragma unroll
                    for (int ms = 0; ms < 2; ms++)
                        mma_tf32(acc[m][ms][j], a[ms][0], a[ms][1], a[ms][2], a[ms][3], b0, b1);
                }
            }
        }
        __syncthreads();
    }

    // ------------------- Epilogue -------------------
    const int b = rowblk >> 10;
    const int s0 = rowblk & 1023;
    const size_t base = (((size_t)b*HH + h)*SS);

    // Q: fp32 direct
    #pragma unroll
    for (int ms = 0; ms < 2; ms++) {
        int r0 = s0 + wm*32 + ms*16 + tg;
        #pragma unroll
        for (int j = 0; j < 2; j++) {
            int c0 = wn*16 + j*8 + tig*2;
            #pragma unroll
            for (int half = 0; half < 2; half++) {
                *(float2*)&g_Qf[(base + r0 + half*8)*DH + c0] =
                    make_float2(acc[0][ms][j][half*2], acc[0][ms][j][half*2+1]);
            }
        }
    }

    // K, V: bounce through smem (fp32, stride 68), emit unit layouts linearly.
    float* Ksm = (float*)psm;                 // [128][68]
    float* Vsm = (float*)psm + 128*68;        // [128][68]
    #pragma unroll
    for (int ms = 0; ms < 2; ms++) {
        int rl = wm*32 + ms*16 + tg;
        #pragma unroll
        for (int j = 0; j < 2; j++) {
            int c0 = wn*16 + j*8 + tig*2;
            #pragma unroll
            for (int half = 0; half < 2; half++) {
                *(float2*)&Ksm[(rl + half*8)*68 + c0] =
                    make_float2(acc[1][ms][j][half*2], acc[1][ms][j][half*2+1]);
                *(float2*)&Vsm[(rl + half*8)*68 + c0] =
                    make_float2(acc[2][ms][j][half*2], acc[2][ms][j][half*2+1]);
            }
        }
    }
    __syncthreads();

    // Kf: 4096 8B units {k(c), k(c+4)} (c = k8*8+tgu), linear stores
    {
        uint32_t* kf = g_Kf + (base + s0)*DH;
        #pragma unroll
        for (int u = 0; u < 8; u++) {
            int idx = tid + u*512;            // 0..4095
            int sl = idx >> 5, un = idx & 31;
            int k8 = un >> 2, tgu = un & 3;
            int c = k8*8 + tgu;
            float f0 = Ksm[sl*68 + c];
            float f1 = Ksm[sl*68 + c + 4];
            *(uint2*)&kf[(size_t)sl*64 + un*2] = make_uint2(f2tf32(f0), f2tf32(f1));
        }
    }
    // Vf: 4096 8B units {v(s), v(s+4)}
    {
        uint32_t* vf = g_Vf + ((size_t)b*HH + h) * (DH*SS);
        #pragma unroll
        for (int u = 0; u < 8; u++) {
            int idx = tid + u*512;            // 0..4095
            int e = idx >> 6, rem = idx & 63;
            int ks8l = rem >> 2, tgu = rem & 3;
            int sl = ks8l*8 + tgu;
            float f0 = Vsm[(sl    )*68 + e];
            float f1 = Vsm[(sl + 4)*68 + e];
            *(uint2*)&vf[(size_t)e*1024 + ((s0 >> 3) + ks8l)*8 + tgu*2] =
                make_uint2(f2tf32(f0), f2tf32(f1));
        }
    }
}

// ---------------------------------------------------------------------------
// Kernel 2: tensor-core causal flash attention (unchanged from round 6).
// grid (16, 12, 4); 128 threads; cp.async 2-stage; 2 CTAs/SM.
// ---------------------------------------------------------------------------
#define STW 8192     // words per stage: K 4096 + V 4096

__global__ __launch_bounds__(128, 2)
void attn_kernel(float* __restrict__ out) {
    extern __shared__ uint32_t smu[];

    const int mt = gridDim.x - 1 - blockIdx.x;
    const int h = blockIdx.y, b = blockIdx.z;
    const int tid = threadIdx.x, wid = tid >> 5, lane = tid & 31;
    const int tg = lane >> 2, tig = lane & 3;
    const int m0 = mt * 64;
    const size_t bh = ((size_t)b*HH + h) * SS;
    const float*    gqf = g_Qf + bh*DH;
    const uint32_t* gkf = g_Kf + bh*DH;
    const uint32_t* gvf = g_Vf + ((size_t)b*HH + h) * (DH*SS);

    const uint32_t smem_base = (uint32_t)__cvta_generic_to_shared(smu);

    uint32_t qb[8][4], qs[8][4];
    {
        const int r0 = m0 + wid*16 + tg;
        #pragma unroll
        for (int k = 0; k < 8; k++) {
            float f[4];
            f[0] = gqf[(size_t)(r0    )*DH + k*8 + tig    ];
            f[1] = gqf[(size_t)(r0 + 8)*DH + k*8 + tig    ];
            f[2] = gqf[(size_t)(r0    )*DH + k*8 + tig + 4];
            f[3] = gqf[(size_t)(r0 + 8)*DH + k*8 + tig + 4];
            #pragma unroll
            for (int i = 0; i < 4; i++) {
                qb[k][i] = f2tf32(f[i]);
                qs[k][i] = f2tf32(f[i] - __uint_as_float(qb[k][i]));
            }
        }
    }

    auto copy_tile = [&](int kt, int stage) {
        const uint32_t sb = smem_base + stage * (STW*4);
        #pragma unroll
        for (int u = 0; u < 8; u++) {
            int idx = tid + u*128;
            int s = idx >> 4, cc = idx & 15;
            int ccs = cc ^ ((s & 7) << 1);
            cpa16(sb + s*256 + ccs*16,
                  gkf + ((size_t)(kt*64 + s)*64 + cc*4));
        }
        #pragma unroll
        for (int u = 0; u < 8; u++) {
            int idx = tid + u*128;
            int e = idx >> 4, p = idx & 15;
            int un = 2*p;
            int usw = un ^ ((e & 7) << 2);
            cpa16(sb + 4096*4 + (e*32 + usw)*8,
                  gvf + (size_t)e*1024 + (kt*32 + un)*2);
        }
        cpa_commit();
    };

    float o[8][4];
    #pragma unroll
    for (int j = 0; j < 8; j++)
        #pragma unroll
        for (int i = 0; i < 4; i++) o[j][i] = 0.f;
    float mrow[2] = {-1e30f, -1e30f};
    float lrow[2] = {0.f, 0.f};

    copy_tile(0, 0);

    for (int kt = 0; kt <= mt; kt++) {
        if (kt < mt) { copy_tile(kt+1, (kt+1)&1); cpa_wait<1>(); }
        else         { cpa_wait<0>(); }
        __syncthreads();

        const uint32_t* Kst = smu + (kt&1)*STW;
        const uint32_t* Vst = Kst + 4096;

        float c[8][4];
        #pragma unroll
        for (int j = 0; j < 8; j++)
            #pragma unroll
            for (int i = 0; i < 4; i++) c[j][i] = 0.f;

        #pragma unroll
        for (int k = 0; k < 8; k++) {
            const int usw = (k*4 + tig) ^ (tg << 2);
            #pragma unroll
            for (int j = 0; j < 8; j++) {
                const int nr = j*8 + tg;
                uint2 kf = *(const uint2*)&Kst[nr*64 + ((k*2 + (tig>>1)) ^ ((tg & 7) << 1))*8 + (tig&1)*4 - (tig&1)*4 + 0];
                (void)kf;
                // NOTE: load must match store swizzle: unit un=k*4+tig lives in
                // 16B chunk cc=un>>1, swizzled ccs=cc^((s&7)<<1), half=un&1.
                int un = k*4 + tig;
                int cc = un >> 1, half = un & 1;
                int ccs = cc ^ ((nr & 7) << 1);
                uint2 kv = *(const uint2*)&Kst[nr*64 + ccs*4 + half*2];
                mma_tf32(c[j], qb[k][0], qb[k][1], qb[k][2], qb[k][3], kv.x, kv.y);
                mma_tf32(c[j], qs[k][0], qs[k][1], qs[k][2], qs[k][3], kv.x, kv.y);
            }
        }

        const float sc = 0.125f;
        #pragma unroll
        for (int j = 0; j < 8; j++)
            #pragma unroll
            for (int i = 0; i < 4; i++) c[j][i] *= sc;

        if (kt == mt) {
            const int rl0 = wid*16 + tg, rl1 = rl0 + 8;
            #pragma unroll
            for (int j = 0; j < 8; j++) {
                int c0 = j*8 + 2*tig, c1 = c0 + 1;
                if (c0 > rl0) c[j][0] = -1e30f;
                if (c1 > rl0) c[j][1] = -1e30f;
                if (c0 > rl1) c[j][2] = -1e30f;
                if (c1 > rl1) c[j][3] = -1e30f;
            }
        }

        float alpha[2];
        #pragma unroll
        for (int h2 = 0; h2 < 2; h2++) {
            float mx = -1e30f;
            #pragma unroll
            for (int j = 0; j < 8; j++) {
                mx = fmaxf(mx, c[j][h2*2]);
                mx = fmaxf(mx, c[j][h2*2 + 1]);
            }
            mx = fmaxf(mx, __shfl_xor_sync(0xffffffffu, mx, 1));
            mx = fmaxf(mx, __shfl_xor_sync(0xffffffffu, mx, 2));
            float mnew = fmaxf(mrow[h2], mx);
            float sum = 0.f;
            #pragma unroll
            for (int j = 0; j < 8; j++) {
                float p0 = __expf(c[j][h2*2]     - mnew);
                float p1 = __expf(c[j][h2*2 + 1] - mnew);
                c[j][h2*2]     = p0;
                c[j][h2*2 + 1] = p1;
                sum += p0 + p1;
            }
            sum += __shfl_xor_sync(0xffffffffu, sum, 1);
            sum += __shfl_xor_sync(0xffffffffu, sum, 2);
            alpha[h2] = __expf(mrow[h2] - mnew);
            mrow[h2] = mnew;
            lrow[h2] = lrow[h2]*alpha[h2] + sum;
        }

        #pragma unroll
        for (int j = 0; j < 8; j++) {
            o[j][0] *= alpha[0]; o[j][1] *= alpha[0];
            o[j][2] *= alpha[1]; o[j][3] *= alpha[1];
        }

        const int src0 = (tg << 2) + (tig >> 1);
        const int src1 = src0 + 2;
        const bool odd = (tig & 1);
        #pragma unroll
        for (int k = 0; k < 8; k++) {
            float e0 = __shfl_sync(0xffffffffu, c[k][0], src0);
            float o0 = __shfl_sync(0xffffffffu, c[k][1], src0);
            float e1 = __shfl_sync(0xffffffffu, c[k][2], src0);
            float o1 = __shfl_sync(0xffffffffu, c[k][3], src0);
            float e2 = __shfl_sync(0xffffffffu, c[k][0], src1);
            float o2 = __shfl_sync(0xffffffffu, c[k][1], src1);
            float e3 = __shfl_sync(0xffffffffu, c[k][2], src1);
            float o3 = __shfl_sync(0xffffffffu, c[k][3], src1);
            uint32_t a0 = f2tf32(odd ? o0 : e0);
            uint32_t a1 = f2tf32(odd ? o1 : e1);
            uint32_t a2 = f2tf32(odd ? o2 : e2);
            uint32_t a3 = f2tf32(odd ? o3 : e3);

            const int usw = (k*4 + tig) ^ (tg << 2);
            #pragma unroll
            for (int jn = 0; jn < 8; jn++) {
                const int e = jn*8 + tg;
                uint2 vf = *(const uint2*)&Vst[(e*32 + usw)*2];
                mma_tf32(o[jn], a0, a1, a2, a3, vf.x, vf.y);
            }
        }
        __syncthreads();
    }

    const float inv0 = 1.f / lrow[0], inv1 = 1.f / lrow[1];
    const int r0 = m0 + wid*16 + tg;
    #pragma unroll
    for (int j = 0; j < 8; j++) {
        int col = h*DH + j*8 + 2*tig;
        *(float2*)&out[((size_t)b*SS + r0    )*(HH*DH) + col] =
            make_float2(o[j][0]*inv0, o[j][1]*inv0);
        *(float2*)&out[((size_t)b*SS + r0 + 8)*(HH*DH) + col] =
            make_float2(o[j][2]*inv1, o[j][3]*inv1);
    }
}

// ---------------------------------------------------------------------------
extern "C" void kernel_launch(void* const* d_in, const int* in_sizes, int n_in,
                              void* d_out, int out_size) {
    const float* x  = (const float*)d_in[0];
    const float* Wq = (const float*)d_in[1];
    const float* Wk = (const float*)d_in[2];
    const float* Wv = (const float*)d_in[3];
    float* out = (float*)d_out;

    round_kernel<<<1184, 256>>>((const uint4*)x, (const uint4*)Wq,
                                (const uint4*)Wk, (const uint4*)Wv);

    const int proj_smem = 3 * PSTG * (int)sizeof(uint32_t);        // 138,240 B
    cudaFuncSetAttribute(qkv_proj_kernel, cudaFuncAttributeMaxDynamicSharedMemorySize,
                         proj_smem);
    qkv_proj_kernel<<<dim3((BB*SS)/128, HH), 512, proj_smem>>>();

    const int attn_smem = 2 * STW * (int)sizeof(uint32_t);          // 65,536 B
    cudaFuncSetAttribute(attn_kernel, cudaFuncAttributeMaxDynamicSharedMemorySize,
                         attn_smem);
    attn_kernel<<<dim3(SS/64, HH, BB), 128, attn_smem>>>(out);
}